// round 7
// baseline (speedup 1.0000x reference)
#include <cuda_runtime.h>
#include <cstdint>

// DeltaSynapse: I[b,o] = sum_e Weff[b,e,o] * sum_d (Xd[d,b,e]*(Wshort[d,b,e]+1)) * delaymap[d,e,o]
// Weff[b,e,o] = sg[e,o]*(W[e,o]*(1-frac[e,o]) + Wlong[b,e,o]*frac[e,o])
//
// D=8, B=16, N=2048. HBM-bound (~417 MB unique -> ~55-66us floor).
// R6: cp.async.bulk (TMA) + mbarrier 3-stage pipeline. The in-flight DRAM
// buffer lives in SMEM (26KB/stage), not registers -> MLP decoupled from
// register pressure (the coupling that pinned R1-R5 at ~55% DRAM).

#define NN 2048
#define BB 16
#define DD 8
#define ECHUNK 16
#define THREADS 256
#define OTILE 256
#define STAGES 3
#define NSTREAM 26                    // W, frac, dm[8], wl[16]
#define SLICE_B (OTILE * 4)           // 1024 bytes per stream slice
#define STAGE_B (NSTREAM * SLICE_B)   // 26624 bytes per stage
#define COEF_ELEMS (ECHUNK * DD * BB) // 2048 floats
#define SMEM_BYTES (STAGES * STAGE_B + COEF_ELEMS * 4 + ECHUNK * 4 + 2 * STAGES * 8)

__device__ __forceinline__ uint32_t s2u(const void* p) {
    uint32_t a;
    asm("{ .reg .u64 t; cvta.to.shared.u64 t, %1; cvt.u32.u64 %0, t; }"
        : "=r"(a) : "l"(p));
    return a;
}
__device__ __forceinline__ void mbar_init(uint32_t a, uint32_t cnt) {
    asm volatile("mbarrier.init.shared.b64 [%0], %1;" :: "r"(a), "r"(cnt) : "memory");
}
__device__ __forceinline__ void mbar_expect_tx(uint32_t a, uint32_t bytes) {
    asm volatile("mbarrier.arrive.expect_tx.shared.b64 _, [%0], %1;"
                 :: "r"(a), "r"(bytes) : "memory");
}
__device__ __forceinline__ void mbar_arrive(uint32_t a) {
    asm volatile("mbarrier.arrive.shared.b64 _, [%0];" :: "r"(a) : "memory");
}
__device__ __forceinline__ void mbar_wait(uint32_t a, uint32_t parity) {
    asm volatile(
        "{\n\t.reg .pred P;\n"
        "WL_%=:\n\t"
        "mbarrier.try_wait.parity.acquire.cta.shared::cta.b64 P, [%0], %1, 0x989680;\n\t"
        "@P bra WD_%=;\n\t"
        "bra WL_%=;\n"
        "WD_%=:\n\t}"
        :: "r"(a), "r"(parity) : "memory");
}
__device__ __forceinline__ void bulk_g2s(uint32_t dst, const void* src,
                                         uint32_t bytes, uint32_t mbar) {
    asm volatile(
        "cp.async.bulk.shared::cta.global.mbarrier::complete_tx::bytes [%0], [%1], %2, [%3];"
        :: "r"(dst), "l"(src), "r"(bytes), "r"(mbar) : "memory");
}

__global__ void ds_zero_kernel(float* __restrict__ out, int n) {
    int i = blockIdx.x * blockDim.x + threadIdx.x;
    if (i < n) out[i] = 0.0f;
}

__device__ __forceinline__ void issue_stage(
    uint32_t buf_u32, uint32_t full_bar, int s, int e, int o0,
    const float* W, const float* frac,
    const float* delaymap, const float* Wlong)
{
    const long beo = (long)e * NN + o0;
    uint32_t dst = buf_u32 + (uint32_t)s * STAGE_B;
    mbar_expect_tx(full_bar, STAGE_B);
    bulk_g2s(dst + 0 * SLICE_B, W + beo, SLICE_B, full_bar);
    bulk_g2s(dst + 1 * SLICE_B, frac + beo, SLICE_B, full_bar);
#pragma unroll
    for (int d = 0; d < DD; d++)
        bulk_g2s(dst + (2 + d) * SLICE_B, delaymap + (long)d * NN * NN + beo,
                 SLICE_B, full_bar);
#pragma unroll
    for (int b = 0; b < BB; b++)
        bulk_g2s(dst + (10 + b) * SLICE_B, Wlong + (long)b * NN * NN + beo,
                 SLICE_B, full_bar);
}

__global__ __launch_bounds__(THREADS, 2) void ds_main_kernel(
    const float* __restrict__ W,         // (N,N)
    const float* __restrict__ Wlong,     // (B,N,N)
    const float* __restrict__ Wshort,    // (D,B,N)
    const float* __restrict__ Xd,        // (D,B,N)
    const float* __restrict__ delaymap,  // (D,N,N)
    const float* __restrict__ frac,      // (N,N)
    const float* __restrict__ signs_pre, // (N,)
    float* __restrict__ out)             // (B,N)
{
    extern __shared__ char smem[];
    float*    buf    = (float*)smem;                              // stages
    float*    coef   = (float*)(smem + STAGES * STAGE_B);         // [el][d][b]
    float*    sgn_sh = coef + COEF_ELEMS;
    uint64_t* bars   = (uint64_t*)(sgn_sh + ECHUNK);

    const int tid = threadIdx.x;
    const int o0  = blockIdx.x * OTILE;
    const int o   = o0 + tid;
    const int e0  = blockIdx.y * ECHUNK;

    const uint32_t buf_u32  = s2u(buf);
    const uint32_t bars_u32 = s2u(bars);
#define FULL_BAR(s)  (bars_u32 + (uint32_t)(s) * 8)
#define EMPTY_BAR(s) (bars_u32 + (uint32_t)(STAGES + (s)) * 8)

    if (tid == 0) {
#pragma unroll
        for (int s = 0; s < STAGES; s++) {
            mbar_init(FULL_BAR(s), 1);
            mbar_init(EMPTY_BAR(s), THREADS);
        }
    }
    __syncthreads();

    // Kick the pipeline: prefetch first STAGES e-slices.
    if (tid == 0) {
#pragma unroll
        for (int s = 0; s < STAGES; s++)
            issue_stage(buf_u32, FULL_BAR(s), s, e0 + s, o0, W, frac, delaymap, Wlong);
    }

    // Preload coef (tiny; overlaps with TMA prologue). b fastest in memory.
    for (int idx = tid; idx < COEF_ELEMS; idx += THREADS) {
        int el   = idx % ECHUNK;
        int rest = idx / ECHUNK;
        int b    = rest % BB;
        int d    = rest / BB;
        int gi   = (d * BB + b) * NN + (e0 + el);
        coef[(el * DD + d) * BB + b] = Xd[gi] * (Wshort[gi] + 1.0f);
    }
    if (tid < ECHUNK) {
        float sp = signs_pre[e0 + tid];
        sgn_sh[tid] = (sp > 0.0f) ? 1.0f : ((sp < 0.0f) ? -1.0f : 0.0f);
    }
    __syncthreads();

    const float4* coef4 = (const float4*)coef;

    float acc[BB];
#pragma unroll
    for (int b = 0; b < BB; b++) acc[b] = 0.0f;

    for (int el = 0; el < ECHUNK; el++) {
        const int s = el % STAGES;
        const uint32_t ph = (uint32_t)(el / STAGES) & 1u;
        mbar_wait(FULL_BAR(s), ph);

        const float* st = buf + s * (NSTREAM * OTILE);
        const float w  = st[0 * OTILE + tid];
        const float f  = st[1 * OTILE + tid];
        const float se = sgn_sh[el];
        const float sg = (w > 0.0f) ? se : 0.0f;
        const float cbase = sg * w * (1.0f - f);
        const float fs    = sg * f;

        float dm[DD];
#pragma unroll
        for (int d = 0; d < DD; d++)
            dm[d] = st[(2 + d) * OTILE + tid];

#pragma unroll
        for (int g = 0; g < BB / 4; g++) {
            float4 p = make_float4(0.f, 0.f, 0.f, 0.f);
#pragma unroll
            for (int d = 0; d < DD; d++) {
                const float4 c = coef4[(el * DD + d) * (BB / 4) + g]; // LDS.128 bcast
                p.x = fmaf(dm[d], c.x, p.x);
                p.y = fmaf(dm[d], c.y, p.y);
                p.z = fmaf(dm[d], c.z, p.z);
                p.w = fmaf(dm[d], c.w, p.w);
            }
            const int b0 = 4 * g;
            const float wl0 = st[(10 + b0 + 0) * OTILE + tid];
            const float wl1 = st[(10 + b0 + 1) * OTILE + tid];
            const float wl2 = st[(10 + b0 + 2) * OTILE + tid];
            const float wl3 = st[(10 + b0 + 3) * OTILE + tid];
            acc[b0 + 0] = fmaf(fmaf(fs, wl0, cbase), p.x, acc[b0 + 0]);
            acc[b0 + 1] = fmaf(fmaf(fs, wl1, cbase), p.y, acc[b0 + 1]);
            acc[b0 + 2] = fmaf(fmaf(fs, wl2, cbase), p.z, acc[b0 + 2]);
            acc[b0 + 3] = fmaf(fmaf(fs, wl3, cbase), p.w, acc[b0 + 3]);
        }

        mbar_arrive(EMPTY_BAR(s));   // all threads done reading stage s

        const int nel = el + STAGES;
        if (nel < ECHUNK && tid == 0) {
            mbar_wait(EMPTY_BAR(s), ph);  // all 256 consumed -> slot reusable
            issue_stage(buf_u32, FULL_BAR(s), s, e0 + nel, o0, W, frac, delaymap, Wlong);
        }
    }

#pragma unroll
    for (int b = 0; b < BB; b++)
        atomicAdd(&out[b * NN + o], acc[b]);
}

extern "C" void kernel_launch(void* const* d_in, const int* in_sizes, int n_in,
                              void* d_out, int out_size) {
    const float* W         = (const float*)d_in[0];
    const float* Wlong     = (const float*)d_in[1];
    const float* Wshort    = (const float*)d_in[2];
    const float* Xd        = (const float*)d_in[3];
    const float* delaymap  = (const float*)d_in[4];
    const float* STDP_frac = (const float*)d_in[5];
    const float* signs_pre = (const float*)d_in[6];
    float* out = (float*)d_out;

    cudaFuncSetAttribute(ds_main_kernel,
                         cudaFuncAttributeMaxDynamicSharedMemorySize, SMEM_BYTES);

    ds_zero_kernel<<<(BB * NN + 255) / 256, 256>>>(out, BB * NN);

    dim3 grid(NN / OTILE, NN / ECHUNK); // (8, 128) = 1024 CTAs
    ds_main_kernel<<<grid, THREADS, SMEM_BYTES>>>(W, Wlong, Wshort, Xd, delaymap,
                                                  STDP_frac, signs_pre, out);
}

// round 8
// speedup vs baseline: 1.4920x; 1.4920x over previous
#include <cuda_runtime.h>

// DeltaSynapse: I[b,o] = sum_e Weff[b,e,o] * sum_d (Xd[d,b,e]*(Wshort[d,b,e]+1)) * delaymap[d,e,o]
// Weff[b,e,o] = sg[e,o]*(W[e,o]*(1-frac[e,o]) + Wlong[b,e,o]*frac[e,o])
//
// D=8, B=16, N=2048. HBM-bound (~417 MB unique). R7: stream-locality config —
// 148 CTAs (1/SM, single wave), 512 thr, float2 per thread (OTILE=1024 ->
// 4KB sequential runs per stream), 26 streams/CTA. Fewer, longer, less
// interleaved DRAM streams; warps/SM kept at 16 (R1 optimum).

#define NN 2048
#define BB 16
#define DD 8
#define EC_MAX 28      // 74 chunks x 28 >= 2048 (dynamic tail)
#define THREADS 512
#define OTILE 1024

__global__ void ds_zero_kernel(float* __restrict__ out, int n) {
    int i = blockIdx.x * blockDim.x + threadIdx.x;
    if (i < n) out[i] = 0.0f;
}

__global__ __launch_bounds__(THREADS, 1) void ds_main_kernel(
    const float* __restrict__ W,         // (N,N)
    const float* __restrict__ Wlong,     // (B,N,N)
    const float* __restrict__ Wshort,    // (D,B,N)
    const float* __restrict__ Xd,        // (D,B,N)
    const float* __restrict__ delaymap,  // (D,N,N)
    const float* __restrict__ frac,      // (N,N)
    const float* __restrict__ signs_pre, // (N,)
    float* __restrict__ out)             // (B,N)
{
    __shared__ float coef[EC_MAX][DD][BB]; // b fastest -> LDS.128 broadcast
    __shared__ float sgn_sh[EC_MAX];

    const int tid  = threadIdx.x;
    const int o    = blockIdx.x * OTILE + tid * 2;
    const int e0   = blockIdx.y * EC_MAX;
    const int eend = min(e0 + EC_MAX, NN);
    const int ecnt = eend - e0;

    // Cooperative coef preload (coalesced in e, guarded tail).
    for (int idx = tid; idx < DD * BB * EC_MAX; idx += THREADS) {
        int el   = idx % EC_MAX;
        int rest = idx / EC_MAX;
        int b    = rest % BB;
        int d    = rest / BB;
        if (el < ecnt) {
            int gi = (d * BB + b) * NN + (e0 + el);
            coef[el][d][b] = Xd[gi] * (Wshort[gi] + 1.0f);
        }
    }
    if (tid < ecnt) {
        float sp = signs_pre[e0 + tid];
        sgn_sh[tid] = (sp > 0.0f) ? 1.0f : ((sp < 0.0f) ? -1.0f : 0.0f);
    }
    __syncthreads();

    float2 acc[BB];
#pragma unroll
    for (int b = 0; b < BB; b++) acc[b] = make_float2(0.f, 0.f);

    for (int el = 0; el < ecnt; el++) {
        const int e = e0 + el;
        const long base_eo = (long)e * NN + o;

        const float2 w2 = *(const float2*)(W + base_eo);
        const float2 f2 = *(const float2*)(frac + base_eo);
        const float se = sgn_sh[el];

        const float sgx = (w2.x > 0.0f) ? se : 0.0f;
        const float sgy = (w2.y > 0.0f) ? se : 0.0f;
        float2 cbase, fs;
        cbase.x = sgx * w2.x * (1.0f - f2.x);  fs.x = sgx * f2.x;
        cbase.y = sgy * w2.y * (1.0f - f2.y);  fs.y = sgy * f2.y;

        float2 dm[DD];
#pragma unroll
        for (int d = 0; d < DD; d++)
            dm[d] = *(const float2*)(delaymap + (long)d * NN * NN + base_eo);

        const float4* cel = (const float4*)coef[el];

#pragma unroll
        for (int g = 0; g < BB / 4; g++) {
            float2 p0 = make_float2(0.f, 0.f), p1 = p0, p2 = p0, p3 = p0;
#pragma unroll
            for (int d = 0; d < DD; d++) {
                const float4 c = cel[d * (BB / 4) + g];   // LDS.128 broadcast
                p0.x = fmaf(dm[d].x, c.x, p0.x);  p0.y = fmaf(dm[d].y, c.x, p0.y);
                p1.x = fmaf(dm[d].x, c.y, p1.x);  p1.y = fmaf(dm[d].y, c.y, p1.y);
                p2.x = fmaf(dm[d].x, c.z, p2.x);  p2.y = fmaf(dm[d].y, c.z, p2.y);
                p3.x = fmaf(dm[d].x, c.w, p3.x);  p3.y = fmaf(dm[d].y, c.w, p3.y);
            }
            const int b0 = 4 * g;
            const float2 wl0 = *(const float2*)(Wlong + (long)(b0 + 0) * NN * NN + base_eo);
            const float2 wl1 = *(const float2*)(Wlong + (long)(b0 + 1) * NN * NN + base_eo);
            const float2 wl2 = *(const float2*)(Wlong + (long)(b0 + 2) * NN * NN + base_eo);
            const float2 wl3 = *(const float2*)(Wlong + (long)(b0 + 3) * NN * NN + base_eo);

            acc[b0 + 0].x = fmaf(fmaf(fs.x, wl0.x, cbase.x), p0.x, acc[b0 + 0].x);
            acc[b0 + 0].y = fmaf(fmaf(fs.y, wl0.y, cbase.y), p0.y, acc[b0 + 0].y);
            acc[b0 + 1].x = fmaf(fmaf(fs.x, wl1.x, cbase.x), p1.x, acc[b0 + 1].x);
            acc[b0 + 1].y = fmaf(fmaf(fs.y, wl1.y, cbase.y), p1.y, acc[b0 + 1].y);
            acc[b0 + 2].x = fmaf(fmaf(fs.x, wl2.x, cbase.x), p2.x, acc[b0 + 2].x);
            acc[b0 + 2].y = fmaf(fmaf(fs.y, wl2.y, cbase.y), p2.y, acc[b0 + 2].y);
            acc[b0 + 3].x = fmaf(fmaf(fs.x, wl3.x, cbase.x), p3.x, acc[b0 + 3].x);
            acc[b0 + 3].y = fmaf(fmaf(fs.y, wl3.y, cbase.y), p3.y, acc[b0 + 3].y);
        }
    }

#pragma unroll
    for (int b = 0; b < BB; b++) {
        atomicAdd(&out[b * NN + o + 0], acc[b].x);
        atomicAdd(&out[b * NN + o + 1], acc[b].y);
    }
}

extern "C" void kernel_launch(void* const* d_in, const int* in_sizes, int n_in,
                              void* d_out, int out_size) {
    const float* W         = (const float*)d_in[0];
    const float* Wlong     = (const float*)d_in[1];
    const float* Wshort    = (const float*)d_in[2];
    const float* Xd        = (const float*)d_in[3];
    const float* delaymap  = (const float*)d_in[4];
    const float* STDP_frac = (const float*)d_in[5];
    const float* signs_pre = (const float*)d_in[6];
    float* out = (float*)d_out;

    ds_zero_kernel<<<(BB * NN + 255) / 256, 256>>>(out, BB * NN);

    dim3 grid(NN / OTILE, (NN + EC_MAX - 1) / EC_MAX); // (2, 74) = 148 CTAs
    ds_main_kernel<<<grid, THREADS>>>(W, Wlong, Wshort, Xd, delaymap,
                                      STDP_frac, signs_pre, out);
}

// round 9
// speedup vs baseline: 1.5212x; 1.0196x over previous
#include <cuda_runtime.h>

// DeltaSynapse: I[b,o] = sum_e Weff[b,e,o] * sum_d (Xd[d,b,e]*(Wshort[d,b,e]+1)) * delaymap[d,e,o]
// Weff[b,e,o] = sg[e,o]*(W[e,o]*(1-frac[e,o]) + Wlong[b,e,o]*frac[e,o])
//
// D=8, B=16, N=2048. HBM-bound (~417 MB unique, floor ~52-66us).
// R7 (WIN, 79.9us): 148 CTAs/1 wave, 512 thr, float2/thread, 4KB stream runs.
// R8: tail-straggle fix — 296 half-size tiles (2 waves of 1 CTA/SM) so wave-2
// lands on first-free SMs; plus __ldcs (evict-first) on all read-once streams.
// Stream structure per SM (26 streams, 4KB runs) is unchanged.

#define NN 2048
#define BB 16
#define DD 8
#define EC_MAX 14      // 148 chunks x 14 >= 2048 (dynamic tail)
#define THREADS 512
#define OTILE 1024

__global__ void ds_zero_kernel(float* __restrict__ out, int n) {
    int i = blockIdx.x * blockDim.x + threadIdx.x;
    if (i < n) out[i] = 0.0f;
}

__global__ __launch_bounds__(THREADS, 1) void ds_main_kernel(
    const float* __restrict__ W,         // (N,N)
    const float* __restrict__ Wlong,     // (B,N,N)
    const float* __restrict__ Wshort,    // (D,B,N)
    const float* __restrict__ Xd,        // (D,B,N)
    const float* __restrict__ delaymap,  // (D,N,N)
    const float* __restrict__ frac,      // (N,N)
    const float* __restrict__ signs_pre, // (N,)
    float* __restrict__ out)             // (B,N)
{
    __shared__ float coef[EC_MAX][DD][BB]; // b fastest -> LDS.128 broadcast
    __shared__ float sgn_sh[EC_MAX];

    const int tid  = threadIdx.x;
    const int o    = blockIdx.x * OTILE + tid * 2;
    const int e0   = blockIdx.y * EC_MAX;
    const int eend = min(e0 + EC_MAX, NN);
    const int ecnt = eend - e0;

    // Cooperative coef preload (coalesced in e, guarded tail).
    for (int idx = tid; idx < DD * BB * EC_MAX; idx += THREADS) {
        int el   = idx % EC_MAX;
        int rest = idx / EC_MAX;
        int b    = rest % BB;
        int d    = rest / BB;
        if (el < ecnt) {
            int gi = (d * BB + b) * NN + (e0 + el);
            coef[el][d][b] = Xd[gi] * (Wshort[gi] + 1.0f);
        }
    }
    if (tid < ecnt) {
        float sp = signs_pre[e0 + tid];
        sgn_sh[tid] = (sp > 0.0f) ? 1.0f : ((sp < 0.0f) ? -1.0f : 0.0f);
    }
    __syncthreads();

    float2 acc[BB];
#pragma unroll
    for (int b = 0; b < BB; b++) acc[b] = make_float2(0.f, 0.f);

    for (int el = 0; el < ecnt; el++) {
        const int e = e0 + el;
        const long base_eo = (long)e * NN + o;

        const float2 w2 = __ldcs((const float2*)(W + base_eo));
        const float2 f2 = __ldcs((const float2*)(frac + base_eo));
        const float se = sgn_sh[el];

        const float sgx = (w2.x > 0.0f) ? se : 0.0f;
        const float sgy = (w2.y > 0.0f) ? se : 0.0f;
        float2 cbase, fs;
        cbase.x = sgx * w2.x * (1.0f - f2.x);  fs.x = sgx * f2.x;
        cbase.y = sgy * w2.y * (1.0f - f2.y);  fs.y = sgy * f2.y;

        float2 dm[DD];
#pragma unroll
        for (int d = 0; d < DD; d++)
            dm[d] = __ldcs((const float2*)(delaymap + (long)d * NN * NN + base_eo));

        const float4* cel = (const float4*)coef[el];

#pragma unroll
        for (int g = 0; g < BB / 4; g++) {
            float2 p0 = make_float2(0.f, 0.f), p1 = p0, p2 = p0, p3 = p0;
#pragma unroll
            for (int d = 0; d < DD; d++) {
                const float4 c = cel[d * (BB / 4) + g];   // LDS.128 broadcast
                p0.x = fmaf(dm[d].x, c.x, p0.x);  p0.y = fmaf(dm[d].y, c.x, p0.y);
                p1.x = fmaf(dm[d].x, c.y, p1.x);  p1.y = fmaf(dm[d].y, c.y, p1.y);
                p2.x = fmaf(dm[d].x, c.z, p2.x);  p2.y = fmaf(dm[d].y, c.z, p2.y);
                p3.x = fmaf(dm[d].x, c.w, p3.x);  p3.y = fmaf(dm[d].y, c.w, p3.y);
            }
            const int b0 = 4 * g;
            const float2 wl0 = __ldcs((const float2*)(Wlong + (long)(b0 + 0) * NN * NN + base_eo));
            const float2 wl1 = __ldcs((const float2*)(Wlong + (long)(b0 + 1) * NN * NN + base_eo));
            const float2 wl2 = __ldcs((const float2*)(Wlong + (long)(b0 + 2) * NN * NN + base_eo));
            const float2 wl3 = __ldcs((const float2*)(Wlong + (long)(b0 + 3) * NN * NN + base_eo));

            acc[b0 + 0].x = fmaf(fmaf(fs.x, wl0.x, cbase.x), p0.x, acc[b0 + 0].x);
            acc[b0 + 0].y = fmaf(fmaf(fs.y, wl0.y, cbase.y), p0.y, acc[b0 + 0].y);
            acc[b0 + 1].x = fmaf(fmaf(fs.x, wl1.x, cbase.x), p1.x, acc[b0 + 1].x);
            acc[b0 + 1].y = fmaf(fmaf(fs.y, wl1.y, cbase.y), p1.y, acc[b0 + 1].y);
            acc[b0 + 2].x = fmaf(fmaf(fs.x, wl2.x, cbase.x), p2.x, acc[b0 + 2].x);
            acc[b0 + 2].y = fmaf(fmaf(fs.y, wl2.y, cbase.y), p2.y, acc[b0 + 2].y);
            acc[b0 + 3].x = fmaf(fmaf(fs.x, wl3.x, cbase.x), p3.x, acc[b0 + 3].x);
            acc[b0 + 3].y = fmaf(fmaf(fs.y, wl3.y, cbase.y), p3.y, acc[b0 + 3].y);
        }
    }

#pragma unroll
    for (int b = 0; b < BB; b++) {
        atomicAdd(&out[b * NN + o + 0], acc[b].x);
        atomicAdd(&out[b * NN + o + 1], acc[b].y);
    }
}

extern "C" void kernel_launch(void* const* d_in, const int* in_sizes, int n_in,
                              void* d_out, int out_size) {
    const float* W         = (const float*)d_in[0];
    const float* Wlong     = (const float*)d_in[1];
    const float* Wshort    = (const float*)d_in[2];
    const float* Xd        = (const float*)d_in[3];
    const float* delaymap  = (const float*)d_in[4];
    const float* STDP_frac = (const float*)d_in[5];
    const float* signs_pre = (const float*)d_in[6];
    float* out = (float*)d_out;

    ds_zero_kernel<<<(BB * NN + 255) / 256, 256>>>(out, BB * NN);

    dim3 grid(NN / OTILE, (NN + EC_MAX - 1) / EC_MAX); // (2, 148) = 296 tiles
    ds_main_kernel<<<grid, THREADS>>>(W, Wlong, Wshort, Xd, delaymap,
                                      STDP_frac, signs_pre, out);
}